// round 9
// baseline (speedup 1.0000x reference)
#include <cuda_runtime.h>
#include <math.h>

#define NN 50000
#define D 128
#define EMAX 800000
#define TILE 1024
#define NPART ((NN + TILE - 1) / TILE)   // 49
#define GEMM_BLOCKS ((NN + 63) / 64)     // 782

// ---- device scratch (no allocations allowed; zero-initialized at load) ----
__device__ float g_ga[(size_t)NN * D];
__device__ float g_gb[(size_t)NN * D];
__device__ float g_gc[(size_t)NN * D];
__device__ float g_dinv1[NN];
__device__ float g_dinv2[NN];
__device__ int   g_cnt1[NN];             // kept zeroed by scan_tiles_kernel
__device__ int   g_cnt2[NN];
__device__ int   g_rowptr1[NN + 1];
__device__ int   g_rowptr2[NN + 1];
__device__ int   g_cursor1[NN];
__device__ int   g_cursor2[NN];
__device__ int   g_col1[EMAX];
__device__ int   g_col2[EMAX];
__device__ int   g_part1[NPART];
__device__ int   g_part2[NPART];
__device__ int   g_tc[3][GEMM_BLOCKS];   // tile counters (reset by consumers)

// ---- packed f32x2 helpers (sm_103a) ----
__device__ __forceinline__ unsigned long long pack2(float a) {
    unsigned long long r;
    asm("mov.b64 %0, {%1, %1};" : "=l"(r) : "f"(a));
    return r;
}
__device__ __forceinline__ void fma2(unsigned long long& d,
                                     unsigned long long a, unsigned long long b) {
    asm("fma.rn.f32x2 %0, %1, %2, %0;" : "+l"(d) : "l"(a), "l"(b));
}
__device__ __forceinline__ unsigned long long mul2(unsigned long long a,
                                                   unsigned long long b) {
    unsigned long long d;
    asm("mul.rn.f32x2 %0, %1, %2;" : "=l"(d) : "l"(a), "l"(b));
    return d;
}

// ---------------------------------------------------------------------------
__global__ void count_both_kernel(const int* __restrict__ ei1, int E1,
                                  const int* __restrict__ ei2, int E2,
                                  int* __restrict__ c1, int* __restrict__ c2) {
    int h1 = E1 >> 1, h2 = E2 >> 1;
    int i = blockIdx.x * blockDim.x + threadIdx.x;
    if (i < h1) {
        int2 d = reinterpret_cast<const int2*>(ei1 + E1)[i];
        atomicAdd(&c1[d.x], 1);
        atomicAdd(&c1[d.y], 1);
    } else if (i < h1 + h2) {
        int2 d = reinterpret_cast<const int2*>(ei2 + E2)[i - h1];
        atomicAdd(&c2[d.x], 1);
        atomicAdd(&c2[d.y], 1);
    } else {
        int k = i - h1 - h2;
        if (k == 0 && (E1 & 1)) atomicAdd(&c1[ei1[E1 + E1 - 1]], 1);
        if (k == 1 && (E2 & 1)) atomicAdd(&c2[ei2[E2 + E2 - 1]], 1);
    }
}

__global__ __launch_bounds__(256) void partial_dinv_kernel(
    const int* __restrict__ c1, float* __restrict__ d1, int* __restrict__ p1,
    const int* __restrict__ c2, float* __restrict__ d2, int* __restrict__ p2)
{
    int set = (blockIdx.x >= NPART) ? 1 : 0;
    int b = blockIdx.x - set * NPART;
    const int* c = set ? c2 : c1;
    float* dv    = set ? d2 : d1;
    int* part    = set ? p2 : p1;

    __shared__ int wsum[8];
    int tid = threadIdx.x;
    int base = b * TILE + tid * 4;
    int s = 0;
    #pragma unroll
    for (int k = 0; k < 4; k++) {
        int i = base + k;
        if (i < NN) {
            int v = c[i];
            s += v;
            dv[i] = rsqrtf((float)v + 1.0f);
        }
    }
    #pragma unroll
    for (int off = 16; off > 0; off >>= 1)
        s += __shfl_down_sync(0xFFFFFFFFu, s, off);
    if ((tid & 31) == 0) wsum[tid >> 5] = s;
    __syncthreads();
    if (tid < 8) {
        int t = wsum[tid];
        #pragma unroll
        for (int off = 4; off > 0; off >>= 1)
            t += __shfl_down_sync(0xFFu, t, off);
        if (tid == 0) part[b] = t;
    }
}

__global__ __launch_bounds__(64) void scan_partials_kernel(
    int* __restrict__ p1, int* __restrict__ rp1,
    int* __restrict__ p2, int* __restrict__ rp2)
{
    int* part = blockIdx.x ? p2 : p1;
    int* rp   = blockIdx.x ? rp2 : rp1;
    __shared__ int w0_total;
    int tid = threadIdx.x;
    int lane = tid & 31;
    int wid = tid >> 5;
    int v = (tid < NPART) ? part[tid] : 0;
    int incl = v;
    #pragma unroll
    for (int off = 1; off < 32; off <<= 1) {
        int t = __shfl_up_sync(0xFFFFFFFFu, incl, off);
        if (lane >= off) incl += t;
    }
    if (tid == 31) w0_total = incl;
    __syncthreads();
    if (wid == 1) incl += w0_total;
    if (tid < NPART) part[tid] = incl - v;
    if (tid == NPART - 1) rp[NN] = incl;
}

__global__ __launch_bounds__(1024) void scan_tiles_kernel(
    int* __restrict__ c1, int* __restrict__ rp1, int* __restrict__ cur1,
    const int* __restrict__ p1,
    int* __restrict__ c2, int* __restrict__ rp2, int* __restrict__ cur2,
    const int* __restrict__ p2)
{
    int set = (blockIdx.x >= NPART) ? 1 : 0;
    int b = blockIdx.x - set * NPART;
    int* cnt        = set ? c2 : c1;
    int* rp         = set ? rp2 : rp1;
    int* cur        = set ? cur2 : cur1;
    const int* part = set ? p2 : p1;

    __shared__ int warp_sums[32];
    int tid = threadIdx.x;
    int lane = tid & 31;
    int wid = tid >> 5;
    int i = b * TILE + tid;
    int v = (i < NN) ? cnt[i] : 0;
    int incl = v;
    #pragma unroll
    for (int off = 1; off < 32; off <<= 1) {
        int t = __shfl_up_sync(0xFFFFFFFFu, incl, off);
        if (lane >= off) incl += t;
    }
    if (lane == 31) warp_sums[wid] = incl;
    __syncthreads();
    if (wid == 0) {
        int s = warp_sums[lane];
        #pragma unroll
        for (int off = 1; off < 32; off <<= 1) {
            int t = __shfl_up_sync(0xFFFFFFFFu, s, off);
            if (lane >= off) s += t;
        }
        warp_sums[lane] = s;
    }
    __syncthreads();
    int woff = (wid > 0) ? warp_sums[wid - 1] : 0;
    int excl = incl - v + woff + part[b];
    if (i < NN) { rp[i] = excl; cur[i] = excl; cnt[i] = 0; }
}

// ---------------------------------------------------------------------------
// GEMM tile: 64x128 output, 128 threads, 8x8 per thread, k-split A staging
// (64x64 twice -> 25.6 KB smem total). acc = (A[rows] @ W) * dinv[row].
#define ASW 68
__device__ __forceinline__ void gemm_tile(
    float (*As)[ASW], float (*Ws)[128],
    const float* __restrict__ A, const float* __restrict__ W,
    const float* __restrict__ dinv_next, float* __restrict__ g_out,
    int row_base, int tid)
{
    const int tx = tid & 15;
    const int ty = tid >> 4;
    const int col0 = tx * 8;
    const int row0 = ty * 8;

    unsigned long long acc2[8][4];
    #pragma unroll
    for (int r = 0; r < 8; r++)
        #pragma unroll
        for (int c = 0; c < 4; c++) acc2[r][c] = 0ull;

    #pragma unroll
    for (int half = 0; half < 2; half++) {
        __syncthreads();
        // Stage A half-tile: 64 rows x 64 cols
        #pragma unroll
        for (int i = tid; i < 64 * 16; i += 128) {
            int r = i >> 4, c4 = i & 15;
            float4 v = make_float4(0.f, 0.f, 0.f, 0.f);
            if (row_base + r < NN)
                v = reinterpret_cast<const float4*>(A)
                        [(long)(row_base + r) * 32 + half * 16 + c4];
            *reinterpret_cast<float4*>(&As[r][c4 * 4]) = v;
        }
        for (int kc = 0; kc < 64; kc += 16) {
            __syncthreads();
            #pragma unroll
            for (int i = tid; i < 512; i += 128) {
                int kk = i >> 5, c4 = i & 31;
                reinterpret_cast<float4*>(&Ws[kk][c4 * 4])[0] =
                    reinterpret_cast<const float4*>(W)
                        [(half * 64 + kc + kk) * 32 + c4];
            }
            __syncthreads();

            #pragma unroll
            for (int kk4 = 0; kk4 < 16; kk4 += 4) {
                float4 av[8];
                #pragma unroll
                for (int r = 0; r < 8; r++)
                    av[r] = *reinterpret_cast<const float4*>(&As[row0 + r][kc + kk4]);

                #pragma unroll
                for (int j = 0; j < 4; j++) {
                    union { float4 f; unsigned long long u[2]; } w0, w1;
                    w0.f = *reinterpret_cast<const float4*>(&Ws[kk4 + j][col0]);
                    w1.f = *reinterpret_cast<const float4*>(&Ws[kk4 + j][col0 + 4]);
                    unsigned long long wv[4] = { w0.u[0], w0.u[1], w1.u[0], w1.u[1] };
                    const float* avf = reinterpret_cast<const float*>(av);
                    #pragma unroll
                    for (int r = 0; r < 8; r++) {
                        unsigned long long aa = pack2(avf[r * 4 + j]);
                        fma2(acc2[r][0], aa, wv[0]);
                        fma2(acc2[r][1], aa, wv[1]);
                        fma2(acc2[r][2], aa, wv[2]);
                        fma2(acc2[r][3], aa, wv[3]);
                    }
                }
            }
        }
    }

    #pragma unroll
    for (int r = 0; r < 8; r++) {
        int row = row_base + row0 + r;
        if (row >= NN) continue;
        unsigned long long dd = pack2(dinv_next[row]);
        union { float4 f; unsigned long long u[2]; } o0, o1;
        o0.u[0] = mul2(acc2[r][0], dd);
        o0.u[1] = mul2(acc2[r][1], dd);
        o1.u[0] = mul2(acc2[r][2], dd);
        o1.u[1] = mul2(acc2[r][3], dd);
        long base = (long)row * 32 + (col0 >> 2);
        reinterpret_cast<float4*>(g_out)[base]     = o0.f;
        reinterpret_cast<float4*>(g_out)[base + 1] = o1.f;
    }
}

// Per-node gather (ELU finalize); one warp, one lane = 4 feature cols.
__device__ __forceinline__ float4 gather_node_elu(
    const float4* __restrict__ g, const int* __restrict__ row_ptr,
    const int* __restrict__ col, const float* __restrict__ dinv,
    float4 bb, int node, int lane)
{
    float4 a0 = g[(long)node * 32 + lane];
    float4 a1 = make_float4(0.f, 0.f, 0.f, 0.f);
    float4 a2 = make_float4(0.f, 0.f, 0.f, 0.f);
    float4 a3 = make_float4(0.f, 0.f, 0.f, 0.f);

    int jb = __ldg(&row_ptr[node]);
    int je = __ldg(&row_ptr[node + 1]);
    int j = jb;
    for (; j + 3 < je; j += 4) {
        int s0 = __ldg(&col[j]);
        int s1 = __ldg(&col[j + 1]);
        int s2 = __ldg(&col[j + 2]);
        int s3 = __ldg(&col[j + 3]);
        float4 v0 = g[(long)s0 * 32 + lane];
        float4 v1 = g[(long)s1 * 32 + lane];
        float4 v2 = g[(long)s2 * 32 + lane];
        float4 v3 = g[(long)s3 * 32 + lane];
        a0.x += v0.x; a0.y += v0.y; a0.z += v0.z; a0.w += v0.w;
        a1.x += v1.x; a1.y += v1.y; a1.z += v1.z; a1.w += v1.w;
        a2.x += v2.x; a2.y += v2.y; a2.z += v2.z; a2.w += v2.w;
        a3.x += v3.x; a3.y += v3.y; a3.z += v3.z; a3.w += v3.w;
    }
    for (; j < je; j++) {
        int s = __ldg(&col[j]);
        float4 v = g[(long)s * 32 + lane];
        a0.x += v.x; a0.y += v.y; a0.z += v.z; a0.w += v.w;
    }
    a0.x += a1.x + a2.x + a3.x;
    a0.y += a1.y + a2.y + a3.y;
    a0.z += a1.z + a2.z + a3.z;
    a0.w += a1.w + a2.w + a3.w;

    float dv = dinv[node];
    float o[4] = { fmaf(a0.x, dv, bb.x), fmaf(a0.y, dv, bb.y),
                   fmaf(a0.z, dv, bb.z), fmaf(a0.w, dv, bb.w) };
    #pragma unroll
    for (int k = 0; k < 4; k++) o[k] = (o[k] > 0.0f) ? o[k] : expm1f(o[k]);
    return make_float4(o[0], o[1], o[2], o[3]);
}

// ---------------------------------------------------------------------------
// Overlapped boundary: per tile t, bids [17t..17t+15] gather 4 nodes each
// (producers), bid 17t+16 runs the GEMM for rows [64t,64t+64) (consumer).
// Producers precede their consumer in dispatch order -> deadlock-free.
__global__ __launch_bounds__(128) void overlap_gather_gemm_kernel(
    const float4* __restrict__ g_in, const int* __restrict__ rp,
    const int* __restrict__ colv, const float* __restrict__ dinv_g,
    const float4* __restrict__ bias, float4* __restrict__ act,
    const float* __restrict__ W, const float* __restrict__ dinv_next,
    float* __restrict__ g_out, int* __restrict__ tc)
{
    __shared__ float As[64][ASW];
    __shared__ float Ws[16][128];

    int t = blockIdx.x / 17;
    int r = blockIdx.x - t * 17;
    int tid = threadIdx.x;

    if (r < 16) {
        // Producer: gather 4 nodes (one per warp), write act, signal tile.
        int lane = tid & 31;
        int warp = tid >> 5;
        int node = t * 64 + r * 4 + warp;
        if (node < NN) {
            float4 val = gather_node_elu(g_in, rp, colv, dinv_g,
                                         bias[lane], node, lane);
            act[(long)node * 32 + lane] = val;
        }
        __threadfence();
        __syncthreads();
        if (tid == 0) atomicAdd(&tc[t], 1);
        return;
    }

    // Consumer: spin until all 16 producers of this tile have signalled.
    if (tid == 0) {
        while (atomicAdd(&tc[t], 0) < 16) __nanosleep(128);
        tc[t] = 0;                       // reset for next graph replay
    }
    __syncthreads();
    __threadfence();
    gemm_tile(As, Ws, (const float*)act, W, dinv_next, g_out, t * 64, tid);
}

// ---------------------------------------------------------------------------
// CSR fill overlapped with layer-1 GEMM (independent work, one grid).
__global__ __launch_bounds__(128) void fill_gemm1_kernel(
    const int* __restrict__ ei1, int E1,
    int* __restrict__ cur1, int* __restrict__ col1,
    const int* __restrict__ ei2, int E2,
    int* __restrict__ cur2, int* __restrict__ col2,
    int fill_blocks,
    const float* __restrict__ A, const float* __restrict__ W,
    const float* __restrict__ dinv, float* __restrict__ g)
{
    __shared__ float As[64][ASW];
    __shared__ float Ws[16][128];

    if (blockIdx.x < fill_blocks) {
        int h1 = E1 >> 1, h2 = E2 >> 1;
        int i = blockIdx.x * blockDim.x + threadIdx.x;
        if (i < h1) {
            int2 s = reinterpret_cast<const int2*>(ei1)[i];
            int2 d = reinterpret_cast<const int2*>(ei1 + E1)[i];
            col1[atomicAdd(&cur1[d.x], 1)] = s.x;
            col1[atomicAdd(&cur1[d.y], 1)] = s.y;
        } else if (i < h1 + h2) {
            int2 s = reinterpret_cast<const int2*>(ei2)[i - h1];
            int2 d = reinterpret_cast<const int2*>(ei2 + E2)[i - h1];
            col2[atomicAdd(&cur2[d.x], 1)] = s.x;
            col2[atomicAdd(&cur2[d.y], 1)] = s.y;
        } else {
            int k = i - h1 - h2;
            if (k == 0 && (E1 & 1))
                col1[atomicAdd(&cur1[ei1[E1 + E1 - 1]], 1)] = ei1[E1 - 1];
            if (k == 1 && (E2 & 1))
                col2[atomicAdd(&cur2[ei2[E2 + E2 - 1]], 1)] = ei2[E2 - 1];
        }
        return;
    }
    int row_base = (blockIdx.x - fill_blocks) * 64;
    gemm_tile(As, Ws, A, W, dinv, g, row_base, threadIdx.x);
}

// ---------------------------------------------------------------------------
// Final standalone gather (layer 4, ReLU).
__global__ __launch_bounds__(256) void gather_finalize_relu_kernel(
    const float4* __restrict__ g, const int* __restrict__ row_ptr,
    const int* __restrict__ col, const float* __restrict__ dinv,
    const float4* __restrict__ b, float4* __restrict__ out)
{
    int warp = (blockIdx.x * blockDim.x + threadIdx.x) >> 5;
    int lane = threadIdx.x & 31;
    if (warp >= NN) return;

    float4 a0 = g[(long)warp * 32 + lane];
    float4 a1 = make_float4(0.f, 0.f, 0.f, 0.f);
    float4 a2 = make_float4(0.f, 0.f, 0.f, 0.f);
    float4 a3 = make_float4(0.f, 0.f, 0.f, 0.f);

    int jb = __ldg(&row_ptr[warp]);
    int je = __ldg(&row_ptr[warp + 1]);
    int j = jb;
    for (; j + 3 < je; j += 4) {
        int s0 = __ldg(&col[j]);
        int s1 = __ldg(&col[j + 1]);
        int s2 = __ldg(&col[j + 2]);
        int s3 = __ldg(&col[j + 3]);
        float4 v0 = g[(long)s0 * 32 + lane];
        float4 v1 = g[(long)s1 * 32 + lane];
        float4 v2 = g[(long)s2 * 32 + lane];
        float4 v3 = g[(long)s3 * 32 + lane];
        a0.x += v0.x; a0.y += v0.y; a0.z += v0.z; a0.w += v0.w;
        a1.x += v1.x; a1.y += v1.y; a1.z += v1.z; a1.w += v1.w;
        a2.x += v2.x; a2.y += v2.y; a2.z += v2.z; a2.w += v2.w;
        a3.x += v3.x; a3.y += v3.y; a3.z += v3.z; a3.w += v3.w;
    }
    for (; j < je; j++) {
        int s = __ldg(&col[j]);
        float4 v = g[(long)s * 32 + lane];
        a0.x += v.x; a0.y += v.y; a0.z += v.z; a0.w += v.w;
    }
    a0.x += a1.x + a2.x + a3.x;
    a0.y += a1.y + a2.y + a3.y;
    a0.z += a1.z + a2.z + a3.z;
    a0.w += a1.w + a2.w + a3.w;

    float dv = dinv[warp];
    float4 bb = b[lane];
    float4 o = make_float4(fmaxf(fmaf(a0.x, dv, bb.x), 0.0f),
                           fmaxf(fmaf(a0.y, dv, bb.y), 0.0f),
                           fmaxf(fmaf(a0.z, dv, bb.z), 0.0f),
                           fmaxf(fmaf(a0.w, dv, bb.w), 0.0f));
    out[(long)warp * 32 + lane] = o;
}

// ---------------------------------------------------------------------------
extern "C" void kernel_launch(void* const* d_in, const int* in_sizes, int n_in,
                              void* d_out, int out_size)
{
    const float* x  = (const float*)d_in[0];
    const float* W1 = (const float*)d_in[1]; const float* b1 = (const float*)d_in[2];
    const float* W2 = (const float*)d_in[3]; const float* b2 = (const float*)d_in[4];
    const float* W3 = (const float*)d_in[5]; const float* b3 = (const float*)d_in[6];
    const float* W4 = (const float*)d_in[7]; const float* b4 = (const float*)d_in[8];
    const int* ei1 = (const int*)d_in[9];
    const int* ei2 = (const int*)d_in[10];
    const int E1 = in_sizes[9] / 2;
    const int E2 = in_sizes[10] / 2;

    float *ga, *gb, *gc, *dinv1, *dinv2;
    int *cnt1, *cnt2, *rp1, *rp2, *cur1, *cur2, *col1, *col2, *p1, *p2, *tc;
    cudaGetSymbolAddress((void**)&ga,   g_ga);
    cudaGetSymbolAddress((void**)&gb,   g_gb);
    cudaGetSymbolAddress((void**)&gc,   g_gc);
    cudaGetSymbolAddress((void**)&dinv1, g_dinv1);
    cudaGetSymbolAddress((void**)&dinv2, g_dinv2);
    cudaGetSymbolAddress((void**)&cnt1, g_cnt1);
    cudaGetSymbolAddress((void**)&cnt2, g_cnt2);
    cudaGetSymbolAddress((void**)&rp1,  g_rowptr1);
    cudaGetSymbolAddress((void**)&rp2,  g_rowptr2);
    cudaGetSymbolAddress((void**)&cur1, g_cursor1);
    cudaGetSymbolAddress((void**)&cur2, g_cursor2);
    cudaGetSymbolAddress((void**)&col1, g_col1);
    cudaGetSymbolAddress((void**)&col2, g_col2);
    cudaGetSymbolAddress((void**)&p1,   g_part1);
    cudaGetSymbolAddress((void**)&p2,   g_part2);
    cudaGetSymbolAddress((void**)&tc,   g_tc);

    float* out_z = (float*)d_out;
    float* out_x = (float*)d_out + (long)NN * D;

    const int gat_blocks  = (NN * 32 + 255) / 256;
    const int nedge2 = (E1 >> 1) + (E2 >> 1) + 2;
    const int fill_blocks = (nedge2 + 127) / 128;
    const int ovl_blocks = GEMM_BLOCKS * 17;

    // ---- CSR build ----
    count_both_kernel<<<(nedge2 + 255) / 256, 256>>>(ei1, E1, ei2, E2, cnt1, cnt2);
    partial_dinv_kernel<<<2 * NPART, 256>>>(cnt1, dinv1, p1, cnt2, dinv2, p2);
    scan_partials_kernel<<<2, 64>>>(p1, rp1, p2, rp2);
    scan_tiles_kernel<<<2 * NPART, 1024>>>(cnt1, rp1, cur1, p1, cnt2, rp2, cur2, p2);

    // CSR fill overlapped with layer-1 GEMM: ga = (x @ W1) * dinv1
    fill_gemm1_kernel<<<fill_blocks + GEMM_BLOCKS, 128>>>(
        ei1, E1, cur1, col1, ei2, E2, cur2, col2, fill_blocks,
        x, W1, dinv1, ga);

    // Boundary 1: gather1(ga -> gb, elu) + gemm2(gb -> gc, *dinv2)
    overlap_gather_gemm_kernel<<<ovl_blocks, 128>>>(
        (const float4*)ga, rp1, col1, dinv1, (const float4*)b1, (float4*)gb,
        W2, dinv2, gc, tc + 0 * GEMM_BLOCKS);
    // Boundary 2: gather2(gc -> out_z, elu) + gemm3(out_z -> ga, *dinv1)
    overlap_gather_gemm_kernel<<<ovl_blocks, 128>>>(
        (const float4*)gc, rp2, col2, dinv2, (const float4*)b2, (float4*)out_z,
        W3, dinv1, ga, tc + 1 * GEMM_BLOCKS);
    // Boundary 3: gather3(ga -> gb, elu) + gemm4(gb -> gc, *dinv2)
    overlap_gather_gemm_kernel<<<ovl_blocks, 128>>>(
        (const float4*)ga, rp1, col1, dinv1, (const float4*)b3, (float4*)gb,
        W4, dinv2, gc, tc + 2 * GEMM_BLOCKS);
    // Final gather (relu) -> out_x
    gather_finalize_relu_kernel<<<gat_blocks, 256>>>(
        (const float4*)gc, rp2, col2, dinv2, (const float4*)b4, (float4*)out_x);
}

// round 10
// speedup vs baseline: 1.6912x; 1.6912x over previous
#include <cuda_runtime.h>
#include <math.h>

#define NN 50000
#define D 128
#define EMAX 800000
#define TILE 1024
#define NPART ((NN + TILE - 1) / TILE)   // 49
#define GEMM_BLOCKS ((NN + 63) / 64)     // 782
#define WPAD 136

// ---- device scratch (no allocations allowed; zero-initialized at load) ----
__device__ float g_ga[(size_t)NN * D];
__device__ float g_gb[(size_t)NN * D];
__device__ float g_dinv1[NN];
__device__ float g_dinv2[NN];
__device__ int   g_cnt1[NN];             // kept zeroed by scan_tiles_kernel
__device__ int   g_cnt2[NN];
__device__ int   g_rowptr1[NN + 1];
__device__ int   g_rowptr2[NN + 1];
__device__ int   g_cursor1[NN];
__device__ int   g_cursor2[NN];
__device__ int   g_col1[EMAX];
__device__ int   g_col2[EMAX];
__device__ int   g_part1[NPART];
__device__ int   g_part2[NPART];
__device__ float g_whi[4 * D * D];       // tf32-rounded hi parts of W1..W4
__device__ float g_wlo[4 * D * D];       // tf32-rounded lo parts

// ---- tf32 helpers ----
__device__ __forceinline__ unsigned f2tf32(float f) {
    unsigned r;
    asm("cvt.rna.tf32.f32 %0, %1;" : "=r"(r) : "f"(f));
    return r;
}
__device__ __forceinline__ void mma_tf32(float* c, const unsigned* a,
                                         unsigned b0, unsigned b1) {
    asm volatile(
        "mma.sync.aligned.m16n8k8.row.col.f32.tf32.tf32.f32 "
        "{%0,%1,%2,%3}, {%4,%5,%6,%7}, {%8,%9}, {%0,%1,%2,%3};"
        : "+f"(c[0]), "+f"(c[1]), "+f"(c[2]), "+f"(c[3])
        : "r"(a[0]), "r"(a[1]), "r"(a[2]), "r"(a[3]), "r"(b0), "r"(b1));
}

// ---------------------------------------------------------------------------
// Split all 4 weight matrices into tf32 hi/lo parts (once per launch).
__global__ void split_w_kernel(const float* __restrict__ W1,
                               const float* __restrict__ W2,
                               const float* __restrict__ W3,
                               const float* __restrict__ W4,
                               float* __restrict__ whi, float* __restrict__ wlo)
{
    int i = blockIdx.x * blockDim.x + threadIdx.x;   // < 4*16384
    int l = i >> 14;
    int j = i & 16383;
    const float* W = (l == 0) ? W1 : (l == 1) ? W2 : (l == 2) ? W3 : W4;
    float f = W[j];
    float hf = __uint_as_float(f2tf32(f));
    whi[i] = hf;
    wlo[i] = __uint_as_float(f2tf32(f - hf));
}

// ---------------------------------------------------------------------------
__global__ void count_both_kernel(const int* __restrict__ ei1, int E1,
                                  const int* __restrict__ ei2, int E2,
                                  int* __restrict__ c1, int* __restrict__ c2) {
    int h1 = E1 >> 1, h2 = E2 >> 1;
    int i = blockIdx.x * blockDim.x + threadIdx.x;
    if (i < h1) {
        int2 d = reinterpret_cast<const int2*>(ei1 + E1)[i];
        atomicAdd(&c1[d.x], 1);
        atomicAdd(&c1[d.y], 1);
    } else if (i < h1 + h2) {
        int2 d = reinterpret_cast<const int2*>(ei2 + E2)[i - h1];
        atomicAdd(&c2[d.x], 1);
        atomicAdd(&c2[d.y], 1);
    } else {
        int k = i - h1 - h2;
        if (k == 0 && (E1 & 1)) atomicAdd(&c1[ei1[E1 + E1 - 1]], 1);
        if (k == 1 && (E2 & 1)) atomicAdd(&c2[ei2[E2 + E2 - 1]], 1);
    }
}

__global__ __launch_bounds__(256) void partial_dinv_kernel(
    const int* __restrict__ c1, float* __restrict__ d1, int* __restrict__ p1,
    const int* __restrict__ c2, float* __restrict__ d2, int* __restrict__ p2)
{
    int set = (blockIdx.x >= NPART) ? 1 : 0;
    int b = blockIdx.x - set * NPART;
    const int* c = set ? c2 : c1;
    float* dv    = set ? d2 : d1;
    int* part    = set ? p2 : p1;

    __shared__ int wsum[8];
    int tid = threadIdx.x;
    int base = b * TILE + tid * 4;
    int s = 0;
    #pragma unroll
    for (int k = 0; k < 4; k++) {
        int i = base + k;
        if (i < NN) {
            int v = c[i];
            s += v;
            dv[i] = rsqrtf((float)v + 1.0f);
        }
    }
    #pragma unroll
    for (int off = 16; off > 0; off >>= 1)
        s += __shfl_down_sync(0xFFFFFFFFu, s, off);
    if ((tid & 31) == 0) wsum[tid >> 5] = s;
    __syncthreads();
    if (tid < 8) {
        int t = wsum[tid];
        #pragma unroll
        for (int off = 4; off > 0; off >>= 1)
            t += __shfl_down_sync(0xFFu, t, off);
        if (tid == 0) part[b] = t;
    }
}

__global__ __launch_bounds__(64) void scan_partials_kernel(
    int* __restrict__ p1, int* __restrict__ rp1,
    int* __restrict__ p2, int* __restrict__ rp2)
{
    int* part = blockIdx.x ? p2 : p1;
    int* rp   = blockIdx.x ? rp2 : rp1;
    __shared__ int w0_total;
    int tid = threadIdx.x;
    int lane = tid & 31;
    int wid = tid >> 5;
    int v = (tid < NPART) ? part[tid] : 0;
    int incl = v;
    #pragma unroll
    for (int off = 1; off < 32; off <<= 1) {
        int t = __shfl_up_sync(0xFFFFFFFFu, incl, off);
        if (lane >= off) incl += t;
    }
    if (tid == 31) w0_total = incl;
    __syncthreads();
    if (wid == 1) incl += w0_total;
    if (tid < NPART) part[tid] = incl - v;
    if (tid == NPART - 1) rp[NN] = incl;
}

__global__ __launch_bounds__(1024) void scan_tiles_kernel(
    int* __restrict__ c1, int* __restrict__ rp1, int* __restrict__ cur1,
    const int* __restrict__ p1,
    int* __restrict__ c2, int* __restrict__ rp2, int* __restrict__ cur2,
    const int* __restrict__ p2)
{
    int set = (blockIdx.x >= NPART) ? 1 : 0;
    int b = blockIdx.x - set * NPART;
    int* cnt        = set ? c2 : c1;
    int* rp         = set ? rp2 : rp1;
    int* cur        = set ? cur2 : cur1;
    const int* part = set ? p2 : p1;

    __shared__ int warp_sums[32];
    int tid = threadIdx.x;
    int lane = tid & 31;
    int wid = tid >> 5;
    int i = b * TILE + tid;
    int v = (i < NN) ? cnt[i] : 0;
    int incl = v;
    #pragma unroll
    for (int off = 1; off < 32; off <<= 1) {
        int t = __shfl_up_sync(0xFFFFFFFFu, incl, off);
        if (lane >= off) incl += t;
    }
    if (lane == 31) warp_sums[wid] = incl;
    __syncthreads();
    if (wid == 0) {
        int s = warp_sums[lane];
        #pragma unroll
        for (int off = 1; off < 32; off <<= 1) {
            int t = __shfl_up_sync(0xFFFFFFFFu, s, off);
            if (lane >= off) s += t;
        }
        warp_sums[lane] = s;
    }
    __syncthreads();
    int woff = (wid > 0) ? warp_sums[wid - 1] : 0;
    int excl = incl - v + woff + part[b];
    if (i < NN) { rp[i] = excl; cur[i] = excl; cnt[i] = 0; }
}

// ---------------------------------------------------------------------------
// tf32 GEMM tile: 64x128 output, 256 threads (8 warps as 4x2), 3xTF32.
// g_out[row] = (A[row] @ W) * dinv[row].
__device__ __forceinline__ void gemm_tf32_tile(
    float (*As)[132], float (*Whs)[WPAD], float (*Wls)[WPAD],
    const float* __restrict__ A,
    const float* __restrict__ whi, const float* __restrict__ wlo,
    const float* __restrict__ dinv, float* __restrict__ g_out,
    int row_base, int tid)
{
    // Stage A tile (64x128 fp32)
    #pragma unroll
    for (int i = tid; i < 64 * 32; i += 256) {
        int r = i >> 5, c4 = i & 31;
        float4 v = make_float4(0.f, 0.f, 0.f, 0.f);
        if (row_base + r < NN)
            v = reinterpret_cast<const float4*>(A)[(long)(row_base + r) * 32 + c4];
        *reinterpret_cast<float4*>(&As[r][c4 * 4]) = v;
    }

    const int lane = tid & 31;
    const int wid = tid >> 5;
    const int wm = (wid & 3) * 16;        // warp row offset (4 warps x 16)
    const int wn = (wid >> 2) * 64;       // warp col offset (2 warps x 64)
    const int g = lane >> 2;              // groupID
    const int t = lane & 3;               // threadID_in_group

    float acc[8][4];
    #pragma unroll
    for (int nt = 0; nt < 8; nt++)
        #pragma unroll
        for (int c = 0; c < 4; c++) acc[nt][c] = 0.0f;

    for (int kc = 0; kc < D; kc += 8) {
        __syncthreads();
        // Stage Whi/Wlo chunk (8 k-rows x 128 cols each)
        #pragma unroll
        for (int i = tid; i < 512; i += 256) {
            int m = i >> 8;               // 0 = hi, 1 = lo
            int j = i & 255;
            int r = j >> 5, c4 = j & 31;
            const float4* src = reinterpret_cast<const float4*>(m ? wlo : whi);
            float4 v = src[(kc + r) * 32 + c4];
            float (*dst)[WPAD] = m ? Wls : Whs;
            *reinterpret_cast<float4*>(&dst[r][c4 * 4]) = v;
        }
        __syncthreads();

        // A fragments (m16n8k8 .row): (g,t),(g+8,t),(g,t+4),(g+8,t+4)
        float af[4] = { As[wm + g][kc + t],     As[wm + g + 8][kc + t],
                        As[wm + g][kc + t + 4], As[wm + g + 8][kc + t + 4] };
        unsigned ah[4], al[4];
        #pragma unroll
        for (int q = 0; q < 4; q++) {
            ah[q] = f2tf32(af[q]);
            al[q] = f2tf32(af[q] - __uint_as_float(ah[q]));
        }

        #pragma unroll
        for (int nt = 0; nt < 8; nt++) {
            int c = wn + nt * 8 + g;
            unsigned bh0 = __float_as_uint(Whs[t][c]);
            unsigned bh1 = __float_as_uint(Whs[t + 4][c]);
            unsigned bl0 = __float_as_uint(Wls[t][c]);
            unsigned bl1 = __float_as_uint(Wls[t + 4][c]);
            mma_tf32(acc[nt], ah, bh0, bh1);   // hi*hi
            mma_tf32(acc[nt], ah, bl0, bl1);   // hi*lo
            mma_tf32(acc[nt], al, bh0, bh1);   // lo*hi
        }
    }

    // Epilogue: D frag (g, 2t),(g, 2t+1),(g+8, 2t),(g+8, 2t+1); scale by dinv.
    int r0 = row_base + wm + g;
    int r1 = r0 + 8;
    float d0 = (r0 < NN) ? dinv[r0] : 0.0f;
    float d1 = (r1 < NN) ? dinv[r1] : 0.0f;
    #pragma unroll
    for (int nt = 0; nt < 8; nt++) {
        int c = wn + nt * 8 + t * 2;
        if (r0 < NN)
            *reinterpret_cast<float2*>(&g_out[(long)r0 * D + c]) =
                make_float2(acc[nt][0] * d0, acc[nt][1] * d0);
        if (r1 < NN)
            *reinterpret_cast<float2*>(&g_out[(long)r1 * D + c]) =
                make_float2(acc[nt][2] * d1, acc[nt][3] * d1);
    }
}

// Standalone tf32 GEMM (layers 2-4).
__global__ __launch_bounds__(256) void gemm_tf32_kernel(
    const float* __restrict__ A,
    const float* __restrict__ whi, const float* __restrict__ wlo,
    const float* __restrict__ dinv, float* __restrict__ g_out)
{
    __shared__ float As[64][132];
    __shared__ float Whs[8][WPAD];
    __shared__ float Wls[8][WPAD];
    gemm_tf32_tile(As, Whs, Wls, A, whi, wlo, dinv, g_out,
                   blockIdx.x * 64, threadIdx.x);
}

// CSR fill overlapped with layer-1 GEMM (independent work, one grid).
__global__ __launch_bounds__(256) void fill_gemm1_kernel(
    const int* __restrict__ ei1, int E1,
    int* __restrict__ cur1, int* __restrict__ col1,
    const int* __restrict__ ei2, int E2,
    int* __restrict__ cur2, int* __restrict__ col2,
    int fill_blocks,
    const float* __restrict__ A,
    const float* __restrict__ whi, const float* __restrict__ wlo,
    const float* __restrict__ dinv, float* __restrict__ g_out)
{
    __shared__ float As[64][132];
    __shared__ float Whs[8][WPAD];
    __shared__ float Wls[8][WPAD];

    if (blockIdx.x < fill_blocks) {
        int h1 = E1 >> 1, h2 = E2 >> 1;
        int i = blockIdx.x * blockDim.x + threadIdx.x;
        if (i < h1) {
            int2 s = reinterpret_cast<const int2*>(ei1)[i];
            int2 d = reinterpret_cast<const int2*>(ei1 + E1)[i];
            col1[atomicAdd(&cur1[d.x], 1)] = s.x;
            col1[atomicAdd(&cur1[d.y], 1)] = s.y;
        } else if (i < h1 + h2) {
            int2 s = reinterpret_cast<const int2*>(ei2)[i - h1];
            int2 d = reinterpret_cast<const int2*>(ei2 + E2)[i - h1];
            col2[atomicAdd(&cur2[d.x], 1)] = s.x;
            col2[atomicAdd(&cur2[d.y], 1)] = s.y;
        } else {
            int k = i - h1 - h2;
            if (k == 0 && (E1 & 1))
                col1[atomicAdd(&cur1[ei1[E1 + E1 - 1]], 1)] = ei1[E1 - 1];
            if (k == 1 && (E2 & 1))
                col2[atomicAdd(&cur2[ei2[E2 + E2 - 1]], 1)] = ei2[E2 - 1];
        }
        return;
    }
    gemm_tf32_tile(As, Whs, Wls, A, whi, wlo, dinv, g_out,
                   (blockIdx.x - fill_blocks) * 64, threadIdx.x);
}

// ---------------------------------------------------------------------------
// Gather + finalize: one warp per node, 4-way unrolled (known-good).
__global__ __launch_bounds__(256) void gather_finalize_kernel(
    const float4* __restrict__ g, const int* __restrict__ row_ptr,
    const int* __restrict__ col, const float* __restrict__ dinv,
    const float4* __restrict__ b, float4* __restrict__ out, int relu_mode)
{
    int warp = (blockIdx.x * blockDim.x + threadIdx.x) >> 5;
    int lane = threadIdx.x & 31;
    if (warp >= NN) return;

    long base = (long)warp * 32 + lane;
    float4 a0 = g[base];
    float4 a1 = make_float4(0.f, 0.f, 0.f, 0.f);
    float4 a2 = make_float4(0.f, 0.f, 0.f, 0.f);
    float4 a3 = make_float4(0.f, 0.f, 0.f, 0.f);

    int jb = __ldg(&row_ptr[warp]);
    int je = __ldg(&row_ptr[warp + 1]);
    int j = jb;
    for (; j + 3 < je; j += 4) {
        int s0 = __ldg(&col[j]);
        int s1 = __ldg(&col[j + 1]);
        int s2 = __ldg(&col[j + 2]);
        int s3 = __ldg(&col[j + 3]);
        float4 v0 = g[(long)s0 * 32 + lane];
        float4 v1 = g[(long)s1 * 32 + lane];
        float4 v2 = g[(long)s2 * 32 + lane];
        float4 v3 = g[(long)s3 * 32 + lane];
        a0.x += v0.x; a0.y += v0.y; a0.z += v0.z; a0.w += v0.w;
        a1.x += v1.x; a1.y += v1.y; a1.z += v1.z; a1.w += v1.w;
        a2.x += v2.x; a2.y += v2.y; a2.z += v2.z; a2.w += v2.w;
        a3.x += v3.x; a3.y += v3.y; a3.z += v3.z; a3.w += v3.w;
    }
    for (; j < je; j++) {
        int s = __ldg(&col[j]);
        float4 v = g[(long)s * 32 + lane];
        a0.x += v.x; a0.y += v.y; a0.z += v.z; a0.w += v.w;
    }
    a0.x += a1.x + a2.x + a3.x;
    a0.y += a1.y + a2.y + a3.y;
    a0.z += a1.z + a2.z + a3.z;
    a0.w += a1.w + a2.w + a3.w;

    float dv = dinv[warp];
    float4 bb = b[lane];
    float o[4] = { fmaf(a0.x, dv, bb.x), fmaf(a0.y, dv, bb.y),
                   fmaf(a0.z, dv, bb.z), fmaf(a0.w, dv, bb.w) };
    if (relu_mode) {
        #pragma unroll
        for (int k = 0; k < 4; k++) o[k] = fmaxf(o[k], 0.0f);
    } else {
        #pragma unroll
        for (int k = 0; k < 4; k++) o[k] = (o[k] > 0.0f) ? o[k] : expm1f(o[k]);
    }
    out[base] = make_float4(o[0], o[1], o[2], o[3]);
}

// ---------------------------------------------------------------------------
extern "C" void kernel_launch(void* const* d_in, const int* in_sizes, int n_in,
                              void* d_out, int out_size)
{
    const float* x  = (const float*)d_in[0];
    const float* W1 = (const float*)d_in[1]; const float* b1 = (const float*)d_in[2];
    const float* W2 = (const float*)d_in[3]; const float* b2 = (const float*)d_in[4];
    const float* W3 = (const float*)d_in[5]; const float* b3 = (const float*)d_in[6];
    const float* W4 = (const float*)d_in[7]; const float* b4 = (const float*)d_in[8];
    const int* ei1 = (const int*)d_in[9];
    const int* ei2 = (const int*)d_in[10];
    const int E1 = in_sizes[9] / 2;
    const int E2 = in_sizes[10] / 2;

    float *ga, *gb, *dinv1, *dinv2, *whi, *wlo;
    int *cnt1, *cnt2, *rp1, *rp2, *cur1, *cur2, *col1, *col2, *p1, *p2;
    cudaGetSymbolAddress((void**)&ga,   g_ga);
    cudaGetSymbolAddress((void**)&gb,   g_gb);
    cudaGetSymbolAddress((void**)&dinv1, g_dinv1);
    cudaGetSymbolAddress((void**)&dinv2, g_dinv2);
    cudaGetSymbolAddress((void**)&cnt1, g_cnt1);
    cudaGetSymbolAddress((void**)&cnt2, g_cnt2);
    cudaGetSymbolAddress((void**)&rp1,  g_rowptr1);
    cudaGetSymbolAddress((void**)&rp2,  g_rowptr2);
    cudaGetSymbolAddress((void**)&cur1, g_cursor1);
    cudaGetSymbolAddress((void**)&cur2, g_cursor2);
    cudaGetSymbolAddress((void**)&col1, g_col1);
    cudaGetSymbolAddress((void**)&col2, g_col2);
    cudaGetSymbolAddress((void**)&p1,   g_part1);
    cudaGetSymbolAddress((void**)&p2,   g_part2);
    cudaGetSymbolAddress((void**)&whi,  g_whi);
    cudaGetSymbolAddress((void**)&wlo,  g_wlo);

    float* out_z = (float*)d_out;
    float* out_x = (float*)d_out + (long)NN * D;

    const int gat_blocks  = (NN * 32 + 255) / 256;
    const int nedge2 = (E1 >> 1) + (E2 >> 1) + 2;
    const int fill_blocks = (nedge2 + 255) / 256;

    // ---- W split + CSR build ----
    split_w_kernel<<<4 * D * D / 256, 256>>>(W1, W2, W3, W4, whi, wlo);
    count_both_kernel<<<(nedge2 + 255) / 256, 256>>>(ei1, E1, ei2, E2, cnt1, cnt2);
    partial_dinv_kernel<<<2 * NPART, 256>>>(cnt1, dinv1, p1, cnt2, dinv2, p2);
    scan_partials_kernel<<<2, 64>>>(p1, rp1, p2, rp2);
    scan_tiles_kernel<<<2 * NPART, 1024>>>(cnt1, rp1, cur1, p1, cnt2, rp2, cur2, p2);

    // CSR fill overlapped with layer-1 GEMM: ga = (x @ W1) * dinv1
    fill_gemm1_kernel<<<fill_blocks + GEMM_BLOCKS, 256>>>(
        ei1, E1, cur1, col1, ei2, E2, cur2, col2, fill_blocks,
        x, whi + 0 * D * D, wlo + 0 * D * D, dinv1, ga);

    // gather1 (elu) -> gb
    gather_finalize_kernel<<<gat_blocks, 256>>>(
        (const float4*)ga, rp1, col1, dinv1, (const float4*)b1, (float4*)gb, 0);
    // gemm2: gb -> ga (*dinv2)
    gemm_tf32_kernel<<<GEMM_BLOCKS, 256>>>(gb, whi + 1 * D * D, wlo + 1 * D * D,
                                           dinv2, ga);
    // gather2 (elu) -> out_z
    gather_finalize_kernel<<<gat_blocks, 256>>>(
        (const float4*)ga, rp2, col2, dinv2, (const float4*)b2, (float4*)out_z, 0);
    // gemm3: out_z -> ga (*dinv1)
    gemm_tf32_kernel<<<GEMM_BLOCKS, 256>>>(out_z, whi + 2 * D * D, wlo + 2 * D * D,
                                           dinv1, ga);
    // gather3 (elu) -> gb
    gather_finalize_kernel<<<gat_blocks, 256>>>(
        (const float4*)ga, rp1, col1, dinv1, (const float4*)b3, (float4*)gb, 0);
    // gemm4: gb -> ga (*dinv2)
    gemm_tf32_kernel<<<GEMM_BLOCKS, 256>>>(gb, whi + 3 * D * D, wlo + 3 * D * D,
                                           dinv2, ga);
    // gather4 (relu) -> out_x
    gather_finalize_kernel<<<gat_blocks, 256>>>(
        (const float4*)ga, rp2, col2, dinv2, (const float4*)b4, (float4*)out_x, 1);
}

// round 11
// speedup vs baseline: 1.8575x; 1.0983x over previous
#include <cuda_runtime.h>
#include <cuda_fp16.h>
#include <math.h>

#define NN 50000
#define D 128
#define EMAX 800000
#define TILE 1024
#define NPART ((NN + TILE - 1) / TILE)   // 49
#define GEMM_BLOCKS ((NN + 63) / 64)     // 782
#define WPAD 136

// ---- device scratch (no allocations allowed; zero-initialized at load) ----
__device__ __half g_ga[(size_t)NN * D];  // fp16 message buffers (pre-activation)
__device__ __half g_gb[(size_t)NN * D];
__device__ float g_act[(size_t)NN * D];  // fp32 activation buffer
__device__ float g_dinv1[NN];
__device__ float g_dinv2[NN];
__device__ int   g_cnt1[NN];             // kept zeroed by scan_tiles_kernel
__device__ int   g_cnt2[NN];
__device__ int   g_rowptr1[NN + 1];
__device__ int   g_rowptr2[NN + 1];
__device__ int   g_cursor1[NN];
__device__ int   g_cursor2[NN];
__device__ int   g_col1[EMAX];
__device__ int   g_col2[EMAX];
__device__ int   g_part1[NPART];
__device__ int   g_part2[NPART];
__device__ float g_whi[4 * D * D];       // tf32-rounded hi parts of W1..W4
__device__ float g_wlo[4 * D * D];       // tf32-rounded lo parts

// ---- tf32 helpers ----
__device__ __forceinline__ unsigned f2tf32(float f) {
    unsigned r;
    asm("cvt.rna.tf32.f32 %0, %1;" : "=r"(r) : "f"(f));
    return r;
}
__device__ __forceinline__ void mma_tf32(float* c, const unsigned* a,
                                         unsigned b0, unsigned b1) {
    asm volatile(
        "mma.sync.aligned.m16n8k8.row.col.f32.tf32.tf32.f32 "
        "{%0,%1,%2,%3}, {%4,%5,%6,%7}, {%8,%9}, {%0,%1,%2,%3};"
        : "+f"(c[0]), "+f"(c[1]), "+f"(c[2]), "+f"(c[3])
        : "r"(a[0]), "r"(a[1]), "r"(a[2]), "r"(a[3]), "r"(b0), "r"(b1));
}

// ---------------------------------------------------------------------------
__global__ void split_w_kernel(const float* __restrict__ W1,
                               const float* __restrict__ W2,
                               const float* __restrict__ W3,
                               const float* __restrict__ W4,
                               float* __restrict__ whi, float* __restrict__ wlo)
{
    int i = blockIdx.x * blockDim.x + threadIdx.x;
    int l = i >> 14;
    int j = i & 16383;
    const float* W = (l == 0) ? W1 : (l == 1) ? W2 : (l == 2) ? W3 : W4;
    float f = W[j];
    float hf = __uint_as_float(f2tf32(f));
    whi[i] = hf;
    wlo[i] = __uint_as_float(f2tf32(f - hf));
}

// ---------------------------------------------------------------------------
__global__ void count_both_kernel(const int* __restrict__ ei1, int E1,
                                  const int* __restrict__ ei2, int E2,
                                  int* __restrict__ c1, int* __restrict__ c2) {
    int h1 = E1 >> 1, h2 = E2 >> 1;
    int i = blockIdx.x * blockDim.x + threadIdx.x;
    if (i < h1) {
        int2 d = reinterpret_cast<const int2*>(ei1 + E1)[i];
        atomicAdd(&c1[d.x], 1);
        atomicAdd(&c1[d.y], 1);
    } else if (i < h1 + h2) {
        int2 d = reinterpret_cast<const int2*>(ei2 + E2)[i - h1];
        atomicAdd(&c2[d.x], 1);
        atomicAdd(&c2[d.y], 1);
    } else {
        int k = i - h1 - h2;
        if (k == 0 && (E1 & 1)) atomicAdd(&c1[ei1[E1 + E1 - 1]], 1);
        if (k == 1 && (E2 & 1)) atomicAdd(&c2[ei2[E2 + E2 - 1]], 1);
    }
}

__global__ __launch_bounds__(256) void partial_dinv_kernel(
    const int* __restrict__ c1, float* __restrict__ d1, int* __restrict__ p1,
    const int* __restrict__ c2, float* __restrict__ d2, int* __restrict__ p2)
{
    int set = (blockIdx.x >= NPART) ? 1 : 0;
    int b = blockIdx.x - set * NPART;
    const int* c = set ? c2 : c1;
    float* dv    = set ? d2 : d1;
    int* part    = set ? p2 : p1;

    __shared__ int wsum[8];
    int tid = threadIdx.x;
    int base = b * TILE + tid * 4;
    int s = 0;
    #pragma unroll
    for (int k = 0; k < 4; k++) {
        int i = base + k;
        if (i < NN) {
            int v = c[i];
            s += v;
            dv[i] = rsqrtf((float)v + 1.0f);
        }
    }
    #pragma unroll
    for (int off = 16; off > 0; off >>= 1)
        s += __shfl_down_sync(0xFFFFFFFFu, s, off);
    if ((tid & 31) == 0) wsum[tid >> 5] = s;
    __syncthreads();
    if (tid < 8) {
        int t = wsum[tid];
        #pragma unroll
        for (int off = 4; off > 0; off >>= 1)
            t += __shfl_down_sync(0xFFu, t, off);
        if (tid == 0) part[b] = t;
    }
}

__global__ __launch_bounds__(64) void scan_partials_kernel(
    int* __restrict__ p1, int* __restrict__ rp1,
    int* __restrict__ p2, int* __restrict__ rp2)
{
    int* part = blockIdx.x ? p2 : p1;
    int* rp   = blockIdx.x ? rp2 : rp1;
    __shared__ int w0_total;
    int tid = threadIdx.x;
    int lane = tid & 31;
    int wid = tid >> 5;
    int v = (tid < NPART) ? part[tid] : 0;
    int incl = v;
    #pragma unroll
    for (int off = 1; off < 32; off <<= 1) {
        int t = __shfl_up_sync(0xFFFFFFFFu, incl, off);
        if (lane >= off) incl += t;
    }
    if (tid == 31) w0_total = incl;
    __syncthreads();
    if (wid == 1) incl += w0_total;
    if (tid < NPART) part[tid] = incl - v;
    if (tid == NPART - 1) rp[NN] = incl;
}

__global__ __launch_bounds__(1024) void scan_tiles_kernel(
    int* __restrict__ c1, int* __restrict__ rp1, int* __restrict__ cur1,
    const int* __restrict__ p1,
    int* __restrict__ c2, int* __restrict__ rp2, int* __restrict__ cur2,
    const int* __restrict__ p2)
{
    int set = (blockIdx.x >= NPART) ? 1 : 0;
    int b = blockIdx.x - set * NPART;
    int* cnt        = set ? c2 : c1;
    int* rp         = set ? rp2 : rp1;
    int* cur        = set ? cur2 : cur1;
    const int* part = set ? p2 : p1;

    __shared__ int warp_sums[32];
    int tid = threadIdx.x;
    int lane = tid & 31;
    int wid = tid >> 5;
    int i = b * TILE + tid;
    int v = (i < NN) ? cnt[i] : 0;
    int incl = v;
    #pragma unroll
    for (int off = 1; off < 32; off <<= 1) {
        int t = __shfl_up_sync(0xFFFFFFFFu, incl, off);
        if (lane >= off) incl += t;
    }
    if (lane == 31) warp_sums[wid] = incl;
    __syncthreads();
    if (wid == 0) {
        int s = warp_sums[lane];
        #pragma unroll
        for (int off = 1; off < 32; off <<= 1) {
            int t = __shfl_up_sync(0xFFFFFFFFu, s, off);
            if (lane >= off) s += t;
        }
        warp_sums[lane] = s;
    }
    __syncthreads();
    int woff = (wid > 0) ? warp_sums[wid - 1] : 0;
    int excl = incl - v + woff + part[b];
    if (i < NN) { rp[i] = excl; cur[i] = excl; cnt[i] = 0; }
}

// ---------------------------------------------------------------------------
// tf32 GEMM tile: 64x128 output, 256 threads (8 warps as 4x2), 3xTF32.
// g_out (fp16) = (A[row] @ W) * dinv[row].
__device__ __forceinline__ void gemm_tf32_tile(
    float (*As)[132], float (*Whs)[WPAD], float (*Wls)[WPAD],
    const float* __restrict__ A,
    const float* __restrict__ whi, const float* __restrict__ wlo,
    const float* __restrict__ dinv, __half* __restrict__ g_out,
    int row_base, int tid)
{
    #pragma unroll
    for (int i = tid; i < 64 * 32; i += 256) {
        int r = i >> 5, c4 = i & 31;
        float4 v = make_float4(0.f, 0.f, 0.f, 0.f);
        if (row_base + r < NN)
            v = reinterpret_cast<const float4*>(A)[(long)(row_base + r) * 32 + c4];
        *reinterpret_cast<float4*>(&As[r][c4 * 4]) = v;
    }

    const int lane = tid & 31;
    const int wid = tid >> 5;
    const int wm = (wid & 3) * 16;
    const int wn = (wid >> 2) * 64;
    const int g = lane >> 2;
    const int t = lane & 3;

    float acc[8][4];
    #pragma unroll
    for (int nt = 0; nt < 8; nt++)
        #pragma unroll
        for (int c = 0; c < 4; c++) acc[nt][c] = 0.0f;

    for (int kc = 0; kc < D; kc += 8) {
        __syncthreads();
        #pragma unroll
        for (int i = tid; i < 512; i += 256) {
            int m = i >> 8;
            int j = i & 255;
            int r = j >> 5, c4 = j & 31;
            const float4* src = reinterpret_cast<const float4*>(m ? wlo : whi);
            float4 v = src[(kc + r) * 32 + c4];
            float (*dst)[WPAD] = m ? Wls : Whs;
            *reinterpret_cast<float4*>(&dst[r][c4 * 4]) = v;
        }
        __syncthreads();

        float af[4] = { As[wm + g][kc + t],     As[wm + g + 8][kc + t],
                        As[wm + g][kc + t + 4], As[wm + g + 8][kc + t + 4] };
        unsigned ah[4], al[4];
        #pragma unroll
        for (int q = 0; q < 4; q++) {
            ah[q] = f2tf32(af[q]);
            al[q] = f2tf32(af[q] - __uint_as_float(ah[q]));
        }

        #pragma unroll
        for (int nt = 0; nt < 8; nt++) {
            int c = wn + nt * 8 + g;
            unsigned bh0 = __float_as_uint(Whs[t][c]);
            unsigned bh1 = __float_as_uint(Whs[t + 4][c]);
            unsigned bl0 = __float_as_uint(Wls[t][c]);
            unsigned bl1 = __float_as_uint(Wls[t + 4][c]);
            mma_tf32(acc[nt], ah, bh0, bh1);
            mma_tf32(acc[nt], ah, bl0, bl1);
            mma_tf32(acc[nt], al, bh0, bh1);
        }
    }

    // Epilogue: scale by dinv, convert to fp16 (half2 per thread per nt).
    int r0 = row_base + wm + g;
    int r1 = r0 + 8;
    float d0 = (r0 < NN) ? dinv[r0] : 0.0f;
    float d1 = (r1 < NN) ? dinv[r1] : 0.0f;
    #pragma unroll
    for (int nt = 0; nt < 8; nt++) {
        int c = wn + nt * 8 + t * 2;
        if (r0 < NN) {
            __half2 h = __float22half2_rn(
                make_float2(acc[nt][0] * d0, acc[nt][1] * d0));
            *reinterpret_cast<__half2*>(&g_out[(long)r0 * D + c]) = h;
        }
        if (r1 < NN) {
            __half2 h = __float22half2_rn(
                make_float2(acc[nt][2] * d1, acc[nt][3] * d1));
            *reinterpret_cast<__half2*>(&g_out[(long)r1 * D + c]) = h;
        }
    }
}

// Standalone tf32 GEMM (layers 2-4).
__global__ __launch_bounds__(256) void gemm_tf32_kernel(
    const float* __restrict__ A,
    const float* __restrict__ whi, const float* __restrict__ wlo,
    const float* __restrict__ dinv, __half* __restrict__ g_out)
{
    __shared__ float As[64][132];
    __shared__ float Whs[8][WPAD];
    __shared__ float Wls[8][WPAD];
    gemm_tf32_tile(As, Whs, Wls, A, whi, wlo, dinv, g_out,
                   blockIdx.x * 64, threadIdx.x);
}

// CSR fill overlapped with layer-1 GEMM (independent work, one grid).
__global__ __launch_bounds__(256) void fill_gemm1_kernel(
    const int* __restrict__ ei1, int E1,
    int* __restrict__ cur1, int* __restrict__ col1,
    const int* __restrict__ ei2, int E2,
    int* __restrict__ cur2, int* __restrict__ col2,
    int fill_blocks,
    const float* __restrict__ A,
    const float* __restrict__ whi, const float* __restrict__ wlo,
    const float* __restrict__ dinv, __half* __restrict__ g_out)
{
    __shared__ float As[64][132];
    __shared__ float Whs[8][WPAD];
    __shared__ float Wls[8][WPAD];

    if (blockIdx.x < fill_blocks) {
        int h1 = E1 >> 1, h2 = E2 >> 1;
        int i = blockIdx.x * blockDim.x + threadIdx.x;
        if (i < h1) {
            int2 s = reinterpret_cast<const int2*>(ei1)[i];
            int2 d = reinterpret_cast<const int2*>(ei1 + E1)[i];
            col1[atomicAdd(&cur1[d.x], 1)] = s.x;
            col1[atomicAdd(&cur1[d.y], 1)] = s.y;
        } else if (i < h1 + h2) {
            int2 s = reinterpret_cast<const int2*>(ei2)[i - h1];
            int2 d = reinterpret_cast<const int2*>(ei2 + E2)[i - h1];
            col2[atomicAdd(&cur2[d.x], 1)] = s.x;
            col2[atomicAdd(&cur2[d.y], 1)] = s.y;
        } else {
            int k = i - h1 - h2;
            if (k == 0 && (E1 & 1))
                col1[atomicAdd(&cur1[ei1[E1 + E1 - 1]], 1)] = ei1[E1 - 1];
            if (k == 1 && (E2 & 1))
                col2[atomicAdd(&cur2[ei2[E2 + E2 - 1]], 1)] = ei2[E2 - 1];
        }
        return;
    }
    gemm_tf32_tile(As, Whs, Wls, A, whi, wlo, dinv, g_out,
                   (blockIdx.x - fill_blocks) * 64, threadIdx.x);
}

// ---------------------------------------------------------------------------
// Gather + finalize over fp16 messages: one warp per node, 4-way unrolled.
// Each lane handles 4 features: uint2 load = 4 halves (8 bytes).
__device__ __forceinline__ void acc_half4(float4& a, uint2 raw) {
    __half2 h0 = *reinterpret_cast<__half2*>(&raw.x);
    __half2 h1 = *reinterpret_cast<__half2*>(&raw.y);
    float2 f0 = __half22float2(h0);
    float2 f1 = __half22float2(h1);
    a.x += f0.x; a.y += f0.y; a.z += f1.x; a.w += f1.y;
}

__global__ __launch_bounds__(256) void gather_finalize_kernel(
    const uint2* __restrict__ g, const int* __restrict__ row_ptr,
    const int* __restrict__ col, const float* __restrict__ dinv,
    const float4* __restrict__ b, float4* __restrict__ out,
    float4* __restrict__ out2, int relu_mode)
{
    int warp = (blockIdx.x * blockDim.x + threadIdx.x) >> 5;
    int lane = threadIdx.x & 31;
    if (warp >= NN) return;

    long base = (long)warp * 32 + lane;
    float4 a0 = make_float4(0.f, 0.f, 0.f, 0.f);
    float4 a1 = make_float4(0.f, 0.f, 0.f, 0.f);
    float4 a2 = make_float4(0.f, 0.f, 0.f, 0.f);
    float4 a3 = make_float4(0.f, 0.f, 0.f, 0.f);
    acc_half4(a0, g[base]);                     // self-loop term

    int jb = __ldg(&row_ptr[warp]);
    int je = __ldg(&row_ptr[warp + 1]);
    int j = jb;
    for (; j + 3 < je; j += 4) {
        int s0 = __ldg(&col[j]);
        int s1 = __ldg(&col[j + 1]);
        int s2 = __ldg(&col[j + 2]);
        int s3 = __ldg(&col[j + 3]);
        uint2 v0 = g[(long)s0 * 32 + lane];
        uint2 v1 = g[(long)s1 * 32 + lane];
        uint2 v2 = g[(long)s2 * 32 + lane];
        uint2 v3 = g[(long)s3 * 32 + lane];
        acc_half4(a0, v0);
        acc_half4(a1, v1);
        acc_half4(a2, v2);
        acc_half4(a3, v3);
    }
    for (; j < je; j++) {
        int s = __ldg(&col[j]);
        acc_half4(a0, g[(long)s * 32 + lane]);
    }
    a0.x += a1.x + a2.x + a3.x;
    a0.y += a1.y + a2.y + a3.y;
    a0.z += a1.z + a2.z + a3.z;
    a0.w += a1.w + a2.w + a3.w;

    float dv = dinv[warp];
    float4 bb = b[lane];
    float o[4] = { fmaf(a0.x, dv, bb.x), fmaf(a0.y, dv, bb.y),
                   fmaf(a0.z, dv, bb.z), fmaf(a0.w, dv, bb.w) };
    if (relu_mode) {
        #pragma unroll
        for (int k = 0; k < 4; k++) o[k] = fmaxf(o[k], 0.0f);
    } else {
        #pragma unroll
        for (int k = 0; k < 4; k++) o[k] = (o[k] > 0.0f) ? o[k] : expm1f(o[k]);
    }
    float4 ov = make_float4(o[0], o[1], o[2], o[3]);
    out[base] = ov;
    if (out2) out2[base] = ov;
}

// ---------------------------------------------------------------------------
extern "C" void kernel_launch(void* const* d_in, const int* in_sizes, int n_in,
                              void* d_out, int out_size)
{
    const float* x  = (const float*)d_in[0];
    const float* W1 = (const float*)d_in[1]; const float* b1 = (const float*)d_in[2];
    const float* W2 = (const float*)d_in[3]; const float* b2 = (const float*)d_in[4];
    const float* W3 = (const float*)d_in[5]; const float* b3 = (const float*)d_in[6];
    const float* W4 = (const float*)d_in[7]; const float* b4 = (const float*)d_in[8];
    const int* ei1 = (const int*)d_in[9];
    const int* ei2 = (const int*)d_in[10];
    const int E1 = in_sizes[9] / 2;
    const int E2 = in_sizes[10] / 2;

    __half *ga, *gb;
    float *actp, *dinv1, *dinv2, *whi, *wlo;
    int *cnt1, *cnt2, *rp1, *rp2, *cur1, *cur2, *col1, *col2, *p1, *p2;
    cudaGetSymbolAddress((void**)&ga,   g_ga);
    cudaGetSymbolAddress((void**)&gb,   g_gb);
    cudaGetSymbolAddress((void**)&actp, g_act);
    cudaGetSymbolAddress((void**)&dinv1, g_dinv1);
    cudaGetSymbolAddress((void**)&dinv2, g_dinv2);
    cudaGetSymbolAddress((void**)&cnt1, g_cnt1);
    cudaGetSymbolAddress((void**)&cnt2, g_cnt2);
    cudaGetSymbolAddress((void**)&rp1,  g_rowptr1);
    cudaGetSymbolAddress((void**)&rp2,  g_rowptr2);
    cudaGetSymbolAddress((void**)&cur1, g_cursor1);
    cudaGetSymbolAddress((void**)&cur2, g_cursor2);
    cudaGetSymbolAddress((void**)&col1, g_col1);
    cudaGetSymbolAddress((void**)&col2, g_col2);
    cudaGetSymbolAddress((void**)&p1,   g_part1);
    cudaGetSymbolAddress((void**)&p2,   g_part2);
    cudaGetSymbolAddress((void**)&whi,  g_whi);
    cudaGetSymbolAddress((void**)&wlo,  g_wlo);

    float* out_z = (float*)d_out;
    float* out_x = (float*)d_out + (long)NN * D;

    const int gat_blocks  = (NN * 32 + 255) / 256;
    const int nedge2 = (E1 >> 1) + (E2 >> 1) + 2;
    const int fill_blocks = (nedge2 + 255) / 256;

    // ---- W split + CSR build ----
    split_w_kernel<<<4 * D * D / 256, 256>>>(W1, W2, W3, W4, whi, wlo);
    count_both_kernel<<<(nedge2 + 255) / 256, 256>>>(ei1, E1, ei2, E2, cnt1, cnt2);
    partial_dinv_kernel<<<2 * NPART, 256>>>(cnt1, dinv1, p1, cnt2, dinv2, p2);
    scan_partials_kernel<<<2, 64>>>(p1, rp1, p2, rp2);
    scan_tiles_kernel<<<2 * NPART, 1024>>>(cnt1, rp1, cur1, p1, cnt2, rp2, cur2, p2);

    // CSR fill overlapped with layer-1 GEMM: ga = (x @ W1) * dinv1  (fp16)
    fill_gemm1_kernel<<<fill_blocks + GEMM_BLOCKS, 256>>>(
        ei1, E1, cur1, col1, ei2, E2, cur2, col2, fill_blocks,
        x, whi + 0 * D * D, wlo + 0 * D * D, dinv1, ga);

    // gather1 (elu) -> act
    gather_finalize_kernel<<<gat_blocks, 256>>>(
        (const uint2*)ga, rp1, col1, dinv1, (const float4*)b1,
        (float4*)actp, nullptr, 0);
    // gemm2: act -> gb (*dinv2)
    gemm_tf32_kernel<<<GEMM_BLOCKS, 256>>>(actp, whi + 1 * D * D, wlo + 1 * D * D,
                                           dinv2, gb);
    // gather2 (elu) -> act AND out_z
    gather_finalize_kernel<<<gat_blocks, 256>>>(
        (const uint2*)gb, rp2, col2, dinv2, (const float4*)b2,
        (float4*)actp, (float4*)out_z, 0);
    // gemm3: act -> ga (*dinv1)
    gemm_tf32_kernel<<<GEMM_BLOCKS, 256>>>(actp, whi + 2 * D * D, wlo + 2 * D * D,
                                           dinv1, ga);
    // gather3 (elu) -> act
    gather_finalize_kernel<<<gat_blocks, 256>>>(
        (const uint2*)ga, rp1, col1, dinv1, (const float4*)b3,
        (float4*)actp, nullptr, 0);
    // gemm4: act -> gb (*dinv2)
    gemm_tf32_kernel<<<GEMM_BLOCKS, 256>>>(actp, whi + 3 * D * D, wlo + 3 * D * D,
                                           dinv2, gb);
    // gather4 (relu) -> out_x
    gather_finalize_kernel<<<gat_blocks, 256>>>(
        (const uint2*)gb, rp2, col2, dinv2, (const float4*)b4,
        (float4*)out_x, nullptr, 1);
}